// round 10
// baseline (speedup 1.0000x reference)
#include <cuda_runtime.h>

// LSR_tensor_dot: out[b] = sum_ijk x[b,i,j,k] * T[i,j,k]
// T[i,j,k] = sum_s sum_abc core[a,b,c] * U1_s[i,a] * U2_s[j,b] * U3_s[k,c]
//
// Kernel 1 (build_T, 128 blocks = (i, j-half)): contractions in smem; zeros out[];
//   signals PDL dependents when done.
// Kernel 2 (dot): grid 1184 = 148 SMs x 8 CTAs, one exactly-full wave, launched
//   via PDL so its setup overlaps build_T. 8192 units of 4096 float4; per-warp
//   RED atomics (no block sync). 512 MiB HBM stream = the whole cost.

#define I_DIM 64
#define R_DIM 8
#define SEP_N 4
#define TVOL   (I_DIM * I_DIM * I_DIM)   // 262144 floats
#define ROW4   (TVOL / 4)                // 65536 float4 per row
#define UNIT4  4096                      // float4 per unit (16 KiB of x)
#define UPR    (ROW4 / UNIT4)            // 16 units per row
#define NUNIT  (512 * UPR)               // 8192 units
#define NBLK   1184                      // 148 SMs * 8 CTAs

__device__ float g_T[TVOL];              // 1 MiB, L2-resident during dot

// factors layout: [s][mode][i][r] -> linear: s*1536 + mode*512 + i*8 + r

__global__ void __launch_bounds__(256) lsr_build_T(const float* __restrict__ core,
                                                   const float* __restrict__ factors,
                                                   float* __restrict__ out) {
    const int i    = blockIdx.x >> 1;      // 0..63
    const int jhal = blockIdx.x & 1;       // which half of j
    const int tid  = threadIdx.x;          // 0..255

    // zero d_out (poisoned by harness); 128 blocks x 4 = 512
    if (tid < 4) out[blockIdx.x * 4 + tid] = 0.f;

    __shared__ float s_core[512];              // [a*64 + b*8 + c]
    __shared__ float s_u1[SEP_N][R_DIM];
    __shared__ float s_u2[SEP_N][512];         // [j*8 + b]
    __shared__ float s_u3[SEP_N][512];         // [k*8 + c]
    __shared__ float s_coeff[SEP_N][64];       // [b*8 + c]
    __shared__ float s_D[SEP_N][256];          // [jloc*8 + c], 32 j's per block

    #pragma unroll
    for (int t = tid; t < 512; t += 256) s_core[t] = core[t];
    if (tid < SEP_N * R_DIM) {
        int s = tid >> 3, r = tid & 7;
        s_u1[s][r] = factors[s * 1536 + 0 * 512 + i * R_DIM + r];
    }
    #pragma unroll
    for (int t = tid; t < SEP_N * 512; t += 256) {
        int s = t >> 9, rem = t & 511;
        s_u2[s][rem] = factors[s * 1536 + 1 * 512 + rem];
        s_u3[s][rem] = factors[s * 1536 + 2 * 512 + rem];
    }
    __syncthreads();

    {   // coeff: 256 entries, one per thread
        int s = tid >> 6, b = (tid >> 3) & 7, c = tid & 7;
        float acc = 0.f;
        #pragma unroll
        for (int a = 0; a < R_DIM; a++)
            acc = fmaf(s_u1[s][a], s_core[a * 64 + b * 8 + c], acc);
        s_coeff[s][(b << 3) | c] = acc;
    }
    __syncthreads();

    #pragma unroll
    for (int t = tid; t < SEP_N * 256; t += 256) {   // D: this block's 32 j's
        int s = t >> 8, rem = t & 255;               // rem = jloc*8 + c
        int jloc = rem >> 3, c = rem & 7;
        int j = jhal * 32 + jloc;
        float acc = 0.f;
        #pragma unroll
        for (int b = 0; b < R_DIM; b++)
            acc = fmaf(s_coeff[s][(b << 3) | c], s_u2[s][(j << 3) | b], acc);
        s_D[s][rem] = acc;
    }
    __syncthreads();

    #pragma unroll
    for (int t = tid; t < 2048; t += 256) {          // T: 32 j's x 64 k's
        int jloc = t >> 6, k = t & 63;
        int j = jhal * 32 + jloc;
        float acc = 0.f;
        #pragma unroll
        for (int s = 0; s < SEP_N; s++)
            #pragma unroll
            for (int c = 0; c < R_DIM; c++)
                acc = fmaf(s_D[s][(jloc << 3) | c], s_u3[s][(k << 3) | c], acc);
        g_T[(i << 12) + (j << 6) + k] = acc;
    }

    // PDL: T (and the out[] zeroing) is written -> dependents may consume.
    asm volatile("griddepcontrol.launch_dependents;");
}

// grid 1184, block 256; block p strides units p, p+1184, ...
// Per-warp reduce + RED atomic: no block-level sync anywhere in the loop.
__global__ void __launch_bounds__(256, 8) lsr_dot(const float* __restrict__ x,
                                                  float* __restrict__ out) {
    const int tid = threadIdx.x;
    const float4* __restrict__ tvb = (const float4*)g_T;

    // Wait for build_T's writes (no-op if launched without PDL).
    asm volatile("griddepcontrol.wait;");

    for (int u = blockIdx.x; u < NUNIT; u += NBLK) {
        const int row   = u >> 4;              // u / UPR
        const int chunk = u & (UPR - 1);
        const float4* __restrict__ xv =
            (const float4*)(x + (size_t)row * TVOL) + chunk * UNIT4;
        const float4* __restrict__ tv = tvb + chunk * UNIT4;

        float a0 = 0.f, a1 = 0.f;
        // 4096 float4 per unit: 8 pair-iterations of 2 independent streams.
        #pragma unroll
        for (int i = tid; i < UNIT4; i += 2 * 256) {
            float4 xa = __ldcs(xv + i);
            float4 ta = __ldg(tv + i);
            float4 xb = __ldcs(xv + i + 256);
            float4 tb = __ldg(tv + i + 256);
            a0 = fmaf(xa.x, ta.x, a0); a0 = fmaf(xa.y, ta.y, a0);
            a0 = fmaf(xa.z, ta.z, a0); a0 = fmaf(xa.w, ta.w, a0);
            a1 = fmaf(xb.x, tb.x, a1); a1 = fmaf(xb.y, tb.y, a1);
            a1 = fmaf(xb.z, tb.z, a1); a1 = fmaf(xb.w, tb.w, a1);
        }
        float acc = a0 + a1;

        #pragma unroll
        for (int off = 16; off > 0; off >>= 1)
            acc += __shfl_down_sync(0xffffffffu, acc, off);

        if ((tid & 31) == 0) atomicAdd(out + row, acc);   // RED, no return
    }
}

extern "C" void kernel_launch(void* const* d_in, const int* in_sizes, int n_in,
                              void* d_out, int out_size) {
    const float* x       = (const float*)d_in[0];  // [512, 64,64,64]
    const float* core    = (const float*)d_in[1];  // [8,8,8]
    const float* factors = (const float*)d_in[2];  // [4,3,64,8]
    float* out = (float*)d_out;                    // [512]

    (void)in_sizes; (void)n_in; (void)out_size;

    lsr_build_T<<<2 * I_DIM, 256>>>(core, factors, out);

    // Launch dot with programmatic dependent launch so its setup overlaps
    // build_T; fall back to a plain launch if PDL is unavailable.
    cudaLaunchConfig_t cfg = {};
    cfg.gridDim  = dim3(NBLK);
    cfg.blockDim = dim3(256);
    cudaLaunchAttribute attr[1];
    attr[0].id = cudaLaunchAttributeProgrammaticStreamSerialization;
    attr[0].val.programmaticStreamSerializationAllowed = 1;
    cfg.attrs    = attr;
    cfg.numAttrs = 1;
    if (cudaLaunchKernelEx(&cfg, lsr_dot, x, out) != cudaSuccess) {
        lsr_dot<<<NBLK, 256>>>(x, out);
    }
}

// round 11
// speedup vs baseline: 1.0007x; 1.0007x over previous
#include <cuda_runtime.h>

// LSR_tensor_dot: out[b] = sum_ijk x[b,i,j,k] * T[i,j,k]
// T[i,j,k] = sum_s sum_abc core[a,b,c] * U1_s[i,a] * U2_s[j,b] * U3_s[k,c]
//
// Kernel 1 (build_T, 128 blocks = (i, j-half)): contractions in smem; zeros out[].
// Kernel 2 (dot): grid 1184 = 148 SMs x 8 CTAs, ONE exactly-full wave (plain
//   launch — PDL staggered the wave and regressed, R8 post-mortem). 8192 units
//   of 4096 float4; per-warp shuffle reduce + RED atomic, no block sync.
//   512 MiB HBM stream = the whole cost.

#define I_DIM 64
#define R_DIM 8
#define SEP_N 4
#define TVOL   (I_DIM * I_DIM * I_DIM)   // 262144 floats
#define ROW4   (TVOL / 4)                // 65536 float4 per row
#define UNIT4  4096                      // float4 per unit (16 KiB of x)
#define UPR    (ROW4 / UNIT4)            // 16 units per row
#define NUNIT  (512 * UPR)               // 8192 units
#define NBLK   1184                      // 148 SMs * 8 CTAs

__device__ float g_T[TVOL];              // 1 MiB, L2-resident during dot

// factors layout: [s][mode][i][r] -> linear: s*1536 + mode*512 + i*8 + r

__global__ void __launch_bounds__(256) lsr_build_T(const float* __restrict__ core,
                                                   const float* __restrict__ factors,
                                                   float* __restrict__ out) {
    const int i    = blockIdx.x >> 1;      // 0..63
    const int jhal = blockIdx.x & 1;       // which half of j
    const int tid  = threadIdx.x;          // 0..255

    // zero d_out (poisoned by harness); 128 blocks x 4 = 512
    if (tid < 4) out[blockIdx.x * 4 + tid] = 0.f;

    __shared__ float s_core[512];              // [a*64 + b*8 + c]
    __shared__ float s_u1[SEP_N][R_DIM];
    __shared__ float s_u2[SEP_N][512];         // [j*8 + b]
    __shared__ float s_u3[SEP_N][512];         // [k*8 + c]
    __shared__ float s_coeff[SEP_N][64];       // [b*8 + c]
    __shared__ float s_D[SEP_N][256];          // [jloc*8 + c], 32 j's per block

    #pragma unroll
    for (int t = tid; t < 512; t += 256) s_core[t] = core[t];
    if (tid < SEP_N * R_DIM) {
        int s = tid >> 3, r = tid & 7;
        s_u1[s][r] = factors[s * 1536 + 0 * 512 + i * R_DIM + r];
    }
    #pragma unroll
    for (int t = tid; t < SEP_N * 512; t += 256) {
        int s = t >> 9, rem = t & 511;
        s_u2[s][rem] = factors[s * 1536 + 1 * 512 + rem];
        s_u3[s][rem] = factors[s * 1536 + 2 * 512 + rem];
    }
    __syncthreads();

    {   // coeff: 256 entries, one per thread
        int s = tid >> 6, b = (tid >> 3) & 7, c = tid & 7;
        float acc = 0.f;
        #pragma unroll
        for (int a = 0; a < R_DIM; a++)
            acc = fmaf(s_u1[s][a], s_core[a * 64 + b * 8 + c], acc);
        s_coeff[s][(b << 3) | c] = acc;
    }
    __syncthreads();

    #pragma unroll
    for (int t = tid; t < SEP_N * 256; t += 256) {   // D: this block's 32 j's
        int s = t >> 8, rem = t & 255;               // rem = jloc*8 + c
        int jloc = rem >> 3, c = rem & 7;
        int j = jhal * 32 + jloc;
        float acc = 0.f;
        #pragma unroll
        for (int b = 0; b < R_DIM; b++)
            acc = fmaf(s_coeff[s][(b << 3) | c], s_u2[s][(j << 3) | b], acc);
        s_D[s][rem] = acc;
    }
    __syncthreads();

    #pragma unroll
    for (int t = tid; t < 2048; t += 256) {          // T: 32 j's x 64 k's
        int jloc = t >> 6, k = t & 63;
        int j = jhal * 32 + jloc;
        float acc = 0.f;
        #pragma unroll
        for (int s = 0; s < SEP_N; s++)
            #pragma unroll
            for (int c = 0; c < R_DIM; c++)
                acc = fmaf(s_D[s][(jloc << 3) | c], s_u3[s][(k << 3) | c], acc);
        g_T[(i << 12) + (j << 6) + k] = acc;
    }
}

// grid 1184, block 256; block p strides units p, p+1184, ...
// Per-warp reduce + RED atomic: no block-level sync anywhere in the loop.
__global__ void __launch_bounds__(256, 8) lsr_dot(const float* __restrict__ x,
                                                  float* __restrict__ out) {
    const int tid = threadIdx.x;
    const float4* __restrict__ tvb = (const float4*)g_T;

    for (int u = blockIdx.x; u < NUNIT; u += NBLK) {
        const int row   = u >> 4;              // u / UPR
        const int chunk = u & (UPR - 1);
        const float4* __restrict__ xv =
            (const float4*)(x + (size_t)row * TVOL) + chunk * UNIT4;
        const float4* __restrict__ tv = tvb + chunk * UNIT4;

        float a0 = 0.f, a1 = 0.f;
        // 4096 float4 per unit: 8 pair-iterations of 2 independent streams.
        #pragma unroll
        for (int i = tid; i < UNIT4; i += 2 * 256) {
            float4 xa = __ldcs(xv + i);
            float4 ta = __ldg(tv + i);
            float4 xb = __ldcs(xv + i + 256);
            float4 tb = __ldg(tv + i + 256);
            a0 = fmaf(xa.x, ta.x, a0); a0 = fmaf(xa.y, ta.y, a0);
            a0 = fmaf(xa.z, ta.z, a0); a0 = fmaf(xa.w, ta.w, a0);
            a1 = fmaf(xb.x, tb.x, a1); a1 = fmaf(xb.y, tb.y, a1);
            a1 = fmaf(xb.z, tb.z, a1); a1 = fmaf(xb.w, tb.w, a1);
        }
        float acc = a0 + a1;

        #pragma unroll
        for (int off = 16; off > 0; off >>= 1)
            acc += __shfl_down_sync(0xffffffffu, acc, off);

        if ((tid & 31) == 0) atomicAdd(out + row, acc);   // RED, no return
    }
}

extern "C" void kernel_launch(void* const* d_in, const int* in_sizes, int n_in,
                              void* d_out, int out_size) {
    const float* x       = (const float*)d_in[0];  // [512, 64,64,64]
    const float* core    = (const float*)d_in[1];  // [8,8,8]
    const float* factors = (const float*)d_in[2];  // [4,3,64,8]
    float* out = (float*)d_out;                    // [512]

    (void)in_sizes; (void)n_in; (void)out_size;

    lsr_build_T<<<2 * I_DIM, 256>>>(core, factors, out);
    lsr_dot<<<NBLK, 256>>>(x, out);
}

// round 12
// speedup vs baseline: 1.0789x; 1.0782x over previous
#include <cuda_runtime.h>

// LSR_tensor_dot: out[b] = sum_ijk x[b,i,j,k] * T[i,j,k]
// T[i,j,k] = sum_s sum_abc core[a,b,c] * U1_s[i,a] * U2_s[j,b] * U3_s[k,c]
//
// Kernel 1 (build_T, 128 blocks = (i, j-half)): contractions in smem; zeros out[].
// Kernel 2 (dot): grid 1184 = 148 SMs x 8 CTAs, ONE exactly-full wave.
//   R10 finding: the per-unit __syncthreads is LOAD-BEARING — it keeps the 8
//   warps converged so each 16 KiB unit is read as a compact DRAM burst.
//   Free-running warps (R8/R10) lost ~8% DRAM BW. So: block reduction with the
//   convergence barrier kept; only the trailing sbuf-protection sync removed
//   via parity double-buffering. One atomicAdd per (block, unit).

#define I_DIM 64
#define R_DIM 8
#define SEP_N 4
#define TVOL   (I_DIM * I_DIM * I_DIM)   // 262144 floats
#define ROW4   (TVOL / 4)                // 65536 float4 per row
#define UNIT4  4096                      // float4 per unit (16 KiB of x)
#define UPR    (ROW4 / UNIT4)            // 16 units per row
#define NUNIT  (512 * UPR)               // 8192 units
#define NBLK   1184                      // 148 SMs * 8 CTAs

__device__ float g_T[TVOL];              // 1 MiB, L2-resident during dot

// factors layout: [s][mode][i][r] -> linear: s*1536 + mode*512 + i*8 + r

__global__ void __launch_bounds__(256) lsr_build_T(const float* __restrict__ core,
                                                   const float* __restrict__ factors,
                                                   float* __restrict__ out) {
    const int i    = blockIdx.x >> 1;      // 0..63
    const int jhal = blockIdx.x & 1;       // which half of j
    const int tid  = threadIdx.x;          // 0..255

    // zero d_out (poisoned by harness); 128 blocks x 4 = 512
    if (tid < 4) out[blockIdx.x * 4 + tid] = 0.f;

    __shared__ float s_core[512];              // [a*64 + b*8 + c]
    __shared__ float s_u1[SEP_N][R_DIM];
    __shared__ float s_u2[SEP_N][512];         // [j*8 + b]
    __shared__ float s_u3[SEP_N][512];         // [k*8 + c]
    __shared__ float s_coeff[SEP_N][64];       // [b*8 + c]
    __shared__ float s_D[SEP_N][256];          // [jloc*8 + c], 32 j's per block

    #pragma unroll
    for (int t = tid; t < 512; t += 256) s_core[t] = core[t];
    if (tid < SEP_N * R_DIM) {
        int s = tid >> 3, r = tid & 7;
        s_u1[s][r] = factors[s * 1536 + 0 * 512 + i * R_DIM + r];
    }
    #pragma unroll
    for (int t = tid; t < SEP_N * 512; t += 256) {
        int s = t >> 9, rem = t & 511;
        s_u2[s][rem] = factors[s * 1536 + 1 * 512 + rem];
        s_u3[s][rem] = factors[s * 1536 + 2 * 512 + rem];
    }
    __syncthreads();

    {   // coeff: 256 entries, one per thread
        int s = tid >> 6, b = (tid >> 3) & 7, c = tid & 7;
        float acc = 0.f;
        #pragma unroll
        for (int a = 0; a < R_DIM; a++)
            acc = fmaf(s_u1[s][a], s_core[a * 64 + b * 8 + c], acc);
        s_coeff[s][(b << 3) | c] = acc;
    }
    __syncthreads();

    #pragma unroll
    for (int t = tid; t < SEP_N * 256; t += 256) {   // D: this block's 32 j's
        int s = t >> 8, rem = t & 255;               // rem = jloc*8 + c
        int jloc = rem >> 3, c = rem & 7;
        int j = jhal * 32 + jloc;
        float acc = 0.f;
        #pragma unroll
        for (int b = 0; b < R_DIM; b++)
            acc = fmaf(s_coeff[s][(b << 3) | c], s_u2[s][(j << 3) | b], acc);
        s_D[s][rem] = acc;
    }
    __syncthreads();

    #pragma unroll
    for (int t = tid; t < 2048; t += 256) {          // T: 32 j's x 64 k's
        int jloc = t >> 6, k = t & 63;
        int j = jhal * 32 + jloc;
        float acc = 0.f;
        #pragma unroll
        for (int s = 0; s < SEP_N; s++)
            #pragma unroll
            for (int c = 0; c < R_DIM; c++)
                acc = fmaf(s_D[s][(jloc << 3) | c], s_u3[s][(k << 3) | c], acc);
        g_T[(i << 12) + (j << 6) + k] = acc;
    }
}

// grid 1184, block 256; block p strides units p, p+1184, ...
// Per-unit: converged double-stream load burst -> shuffle reduce -> block
// reduce via parity-double-buffered smem (one sync per unit) -> one atomicAdd.
__global__ void __launch_bounds__(256, 8) lsr_dot(const float* __restrict__ x,
                                                  float* __restrict__ out) {
    const int tid = threadIdx.x;
    const float4* __restrict__ tvb = (const float4*)g_T;
    __shared__ float sbuf[2][8];
    int par = 0;

    for (int u = blockIdx.x; u < NUNIT; u += NBLK) {
        const int row   = u >> 4;              // u / UPR
        const int chunk = u & (UPR - 1);
        const float4* __restrict__ xv =
            (const float4*)(x + (size_t)row * TVOL) + chunk * UNIT4;
        const float4* __restrict__ tv = tvb + chunk * UNIT4;

        float a0 = 0.f, a1 = 0.f;
        // 4096 float4 per unit: 8 pair-iterations of 2 independent streams.
        #pragma unroll
        for (int i = tid; i < UNIT4; i += 2 * 256) {
            float4 xa = __ldcs(xv + i);
            float4 ta = __ldg(tv + i);
            float4 xb = __ldcs(xv + i + 256);
            float4 tb = __ldg(tv + i + 256);
            a0 = fmaf(xa.x, ta.x, a0); a0 = fmaf(xa.y, ta.y, a0);
            a0 = fmaf(xa.z, ta.z, a0); a0 = fmaf(xa.w, ta.w, a0);
            a1 = fmaf(xb.x, tb.x, a1); a1 = fmaf(xb.y, tb.y, a1);
            a1 = fmaf(xb.z, tb.z, a1); a1 = fmaf(xb.w, tb.w, a1);
        }
        float acc = a0 + a1;

        #pragma unroll
        for (int off = 16; off > 0; off >>= 1)
            acc += __shfl_down_sync(0xffffffffu, acc, off);

        if ((tid & 31) == 0) sbuf[par][tid >> 5] = acc;
        __syncthreads();   // convergence barrier (load-bearing, R10) + sbuf publish
        if (tid == 0) {
            const float* sb = sbuf[par];
            float v = (sb[0] + sb[1]) + (sb[2] + sb[3])
                    + (sb[4] + sb[5]) + (sb[6] + sb[7]);
            atomicAdd(out + row, v);
        }
        par ^= 1;          // next unit writes the other buffer — no trailing sync
    }
}

extern "C" void kernel_launch(void* const* d_in, const int* in_sizes, int n_in,
                              void* d_out, int out_size) {
    const float* x       = (const float*)d_in[0];  // [512, 64,64,64]
    const float* core    = (const float*)d_in[1];  // [8,8,8]
    const float* factors = (const float*)d_in[2];  // [4,3,64,8]
    float* out = (float*)d_out;                    // [512]

    (void)in_sizes; (void)n_in; (void)out_size;

    lsr_build_T<<<2 * I_DIM, 256>>>(core, factors, out);
    lsr_dot<<<NBLK, 256>>>(x, out);
}